// round 13
// baseline (speedup 1.0000x reference)
#include <cuda_runtime.h>
#include <cuda_fp16.h>

#define NN 50000
#define EE 800000
#define HHD 4
#define HC 128
#define FIN 64
#define SCAN_B 512
#define SCAN_GRID ((NN + SCAN_B - 1) / SCAN_B)   // 98
#define FOLD_BLOCKS 64

// ---------------- scratch (device globals; zero-initialized at load) --------
__device__ __align__(16) int      g_src[EE];
__device__ __align__(16) int      g_dst[EE];
__device__ __align__(16) int      g_csr_src[EE];
__device__ __align__(16) int      g_deg[NN];       // zero at load; reset by aggregate
__device__ __align__(16) int      g_off[NN];
__device__ __align__(16) int      g_cursor[NN];
__device__ __align__(16) unsigned g_h2[NN * 64];   // h as half2 pairs
__device__ __align__(16) float    g_resid[NN * HC];
__device__ __align__(16) float    g_asrc[NN * HHD];
__device__ __align__(16) float    g_adst[NN * HHD];
__device__ __align__(16) float    g_wa[FIN * 8];   // folded att weights
__device__ int g_gbase;                            // reset by aggregate

// ---------------- helpers ---------------------------------------------------
__device__ __forceinline__ float lrelu(float x) { return x >= 0.f ? x : 0.2f * x; }
__device__ __forceinline__ int clampi(int v) {
    return v < 0 ? 0 : (v >= NN ? NN - 1 : v);
}
__device__ __forceinline__ unsigned f2tf(float f) {
    unsigned u;
    asm("cvt.rna.tf32.f32 %0, %1;" : "=r"(u) : "f"(f));
    return u;
}
__device__ __forceinline__ void mma_tf32(float* d, const unsigned* a,
                                         const unsigned* b) {
    asm volatile(
        "mma.sync.aligned.m16n8k8.row.col.f32.tf32.tf32.f32 "
        "{%0,%1,%2,%3}, {%4,%5,%6,%7}, {%8,%9}, {%0,%1,%2,%3};"
        : "+f"(d[0]), "+f"(d[1]), "+f"(d[2]), "+f"(d[3])
        : "r"(a[0]), "r"(a[1]), "r"(a[2]), "r"(a[3]), "r"(b[0]), "r"(b[1]));
}

// ---------------- fold (64 blocks, warp per output) --------------------------
__global__ void k_fold(const float* __restrict__ W,
                       const float* __restrict__ att_src,
                       const float* __restrict__ att_dst) {
    int o = blockIdx.x * 8 + (threadIdx.x >> 5);   // 0..511
    int c = threadIdx.x & 31;
    int k = o >> 3, j = o & 7, ph = j & 3;
    const float* att = (j < 4) ? att_src : att_dst;
    float v = W[k * HC + ph * 32 + c] * att[ph * 32 + c];
#pragma unroll
    for (int of = 16; of > 0; of >>= 1)
        v += __shfl_xor_sync(0xffffffffu, v, of);
    if (c == 0) g_wa[o] = v;
}

// ---------------- convert: 4 edges/thread, per-thread dtype detect -----------
// Probe is int64-src interpretation: ints [2i, 2i+8) — in-bounds under BOTH
// interpretations (int64 src region == whole int32 buffer size).
__global__ void k_convert(const int* __restrict__ p) {
    int t = blockIdx.x * blockDim.x + threadIdx.x;
    int i = t * 4;
    if (i >= EE) return;
    int4 a0 = ((const int4*)p)[i / 2];        // src edges i..i+1 (int64 view)
    int4 a1 = ((const int4*)p)[i / 2 + 1];    // src edges i+2..i+3
    bool is64 = ((a0.y | a0.w | a1.y | a1.w) == 0) &&
                ((unsigned)a0.x < NN) && ((unsigned)a0.z < NN) &&
                ((unsigned)a1.x < NN) && ((unsigned)a1.z < NN);
    int4 sv, dv;
    if (is64) {
        int4 b0 = ((const int4*)p)[(EE + i) / 2];
        int4 b1 = ((const int4*)p)[(EE + i) / 2 + 1];
        sv = make_int4(a0.x, a0.z, a1.x, a1.z);
        dv = make_int4(b0.x, b0.z, b1.x, b1.z);
    } else {
        sv = ((const int4*)p)[i / 4];
        dv = ((const int4*)p)[(EE + i) / 4];
    }
    sv.x = clampi(sv.x); sv.y = clampi(sv.y); sv.z = clampi(sv.z); sv.w = clampi(sv.w);
    dv.x = clampi(dv.x); dv.y = clampi(dv.y); dv.z = clampi(dv.z); dv.w = clampi(dv.w);
    ((int4*)g_src)[i / 4] = sv;
    ((int4*)g_dst)[i / 4] = dv;
    atomicAdd(&g_deg[dv.x], 1);
    atomicAdd(&g_deg[dv.y], 1);
    atomicAdd(&g_deg[dv.z], 1);
    atomicAdd(&g_deg[dv.w], 1);
}

// ---------------- one-pass scan (atomic base claim) --------------------------
__global__ void __launch_bounds__(SCAN_B) k_scan() {
    __shared__ int wsm[16];
    __shared__ int base;
    const int tid = threadIdx.x, lane = tid & 31, wid = tid >> 5;
    int idx = blockIdx.x * SCAN_B + tid;
    int v = (idx < NN) ? g_deg[idx] : 0;
    int xi = v;
#pragma unroll
    for (int o = 1; o < 32; o <<= 1) {
        int y = __shfl_up_sync(0xffffffffu, xi, o);
        if (lane >= o) xi += y;
    }
    if (lane == 31) wsm[wid] = xi;
    __syncthreads();
    if (wid == 0 && lane < 16) {
        int t = wsm[lane];
#pragma unroll
        for (int o = 1; o < 16; o <<= 1) {
            int y = __shfl_up_sync(0x0000ffffu, t, o);
            if (lane >= o) t += y;
        }
        wsm[lane] = t;
    }
    __syncthreads();
    if (tid == 0) base = atomicAdd(&g_gbase, wsm[15]);
    __syncthreads();
    int woff = (wid == 0) ? 0 : wsm[wid - 1];
    if (idx < NN) {
        int o = base + woff + xi - v;
        g_off[idx] = o;
        g_cursor[idx] = o;
    }
}

// ---------------- scatter: 4 edges per thread --------------------------------
__global__ void k_scatter() {
    int t = blockIdx.x * blockDim.x + threadIdx.x;
    int i = t * 4;
    if (i >= EE) return;
    int4 sv = ((const int4*)g_src)[i / 4];
    int4 dv = ((const int4*)g_dst)[i / 4];
    int p0 = atomicAdd(&g_cursor[dv.x], 1);
    int p1 = atomicAdd(&g_cursor[dv.y], 1);
    int p2 = atomicAdd(&g_cursor[dv.z], 1);
    int p3 = atomicAdd(&g_cursor[dv.w], 1);
    g_csr_src[p0] = sv.x;
    g_csr_src[p1] = sv.y;
    g_csr_src[p2] = sv.z;
    g_csr_src[p3] = sv.w;
}

// ---------------- TF32 tensor-core GEMM + att scalars ------------------------
// [NN x 64] @ [64 x 256], M-tile 128, 512 threads = 16 warps (4M x 4N).
#define SX 68
#define SW 264
#define GEMM_SMEM ((128 * SX + 64 * SW + 512) * 4)   // 104448 B

__global__ void __launch_bounds__(512) k_gemm_mma(
        const float* __restrict__ x, const float* __restrict__ W,
        const float* __restrict__ res_w, const float* __restrict__ res_b) {
    extern __shared__ unsigned sh[];
    unsigned* xs  = sh;                                 // 128 x SX (tf32 bits)
    unsigned* ws  = sh + 128 * SX;                      // 64 x SW (tf32 bits)
    float*    was = (float*)(sh + 128 * SX + 64 * SW);  // 512

    const int tid  = threadIdx.x;
    const int row0 = blockIdx.x * 128;

    if (tid < FIN * 8) was[tid] = g_wa[tid];
    for (int i = tid; i < FIN * 32; i += 512) {
        int k = i >> 5, q = i & 31;
        float4 w1 = ((const float4*)W)[k * 32 + q];
        float4 w2 = ((const float4*)res_w)[k * 32 + q];
        unsigned* p1 = &ws[k * SW + 4 * q];
        unsigned* p2 = &ws[k * SW + 128 + 4 * q];
        p1[0] = f2tf(w1.x); p1[1] = f2tf(w1.y); p1[2] = f2tf(w1.z); p1[3] = f2tf(w1.w);
        p2[0] = f2tf(w2.x); p2[1] = f2tf(w2.y); p2[2] = f2tf(w2.z); p2[3] = f2tf(w2.w);
    }
    for (int i = tid; i < 128 * 16; i += 512) {
        int r = i >> 4, q = i & 15;
        int row = row0 + r;
        float4 xv = (row < NN) ? ((const float4*)x)[row * 16 + q]
                               : make_float4(0.f, 0.f, 0.f, 0.f);
        unsigned* p = &xs[r * SX + 4 * q];
        p[0] = f2tf(xv.x); p[1] = f2tf(xv.y); p[2] = f2tf(xv.z); p[3] = f2tf(xv.w);
    }
    __syncthreads();

    const int warp = tid >> 5, lane = tid & 31;
    const int mw = warp >> 2, nw = warp & 3;             // 4 x 4 warp grid
    const int grp = lane >> 2, tig = lane & 3;
    const int mbase = mw * 32, nbase = nw * 64;

    float acc[2][8][4];
#pragma unroll
    for (int mt = 0; mt < 2; mt++)
#pragma unroll
        for (int nt = 0; nt < 8; nt++)
#pragma unroll
            for (int e = 0; e < 4; e++) acc[mt][nt][e] = 0.f;

#pragma unroll
    for (int kt = 0; kt < 8; kt++) {
        const int k0 = kt * 8;
        unsigned afr[2][4], bfr[8][2];
#pragma unroll
        for (int mt = 0; mt < 2; mt++) {
            int base = (mbase + mt * 16 + grp) * SX + k0 + tig;
            afr[mt][0] = xs[base];
            afr[mt][1] = xs[base + 8 * SX];
            afr[mt][2] = xs[base + 4];
            afr[mt][3] = xs[base + 8 * SX + 4];
        }
#pragma unroll
        for (int nt = 0; nt < 8; nt++) {
            int bb = (k0 + tig) * SW + nbase + nt * 8 + grp;
            bfr[nt][0] = ws[bb];
            bfr[nt][1] = ws[bb + 4 * SW];
        }
#pragma unroll
        for (int mt = 0; mt < 2; mt++)
#pragma unroll
            for (int nt = 0; nt < 8; nt++)
                mma_tf32(acc[mt][nt], afr[mt], bfr[nt]);
    }

    // epilogue: nw 0,1 -> g_h2 (fp16) ; nw 2,3 -> g_resid (fp32, +res_b)
#pragma unroll
    for (int mt = 0; mt < 2; mt++) {
        int r0 = row0 + mbase + mt * 16 + grp;
#pragma unroll
        for (int nt = 0; nt < 8; nt++) {
            int col = nbase + nt * 8 + 2 * tig;
            float v00 = acc[mt][nt][0], v01 = acc[mt][nt][1];
            float v10 = acc[mt][nt][2], v11 = acc[mt][nt][3];
            if (nw < 2) {
                int cp = col >> 1;
                if (r0 < NN)
                    *(__half2*)&g_h2[r0 * 64 + cp] = __floats2half2_rn(v00, v01);
                if (r0 + 8 < NN)
                    *(__half2*)&g_h2[(r0 + 8) * 64 + cp] = __floats2half2_rn(v10, v11);
            } else {
                int cr = col - HC;
                float b0 = res_b[cr], b1 = res_b[cr + 1];
                if (r0 < NN)
                    *(float2*)&g_resid[r0 * HC + cr] = make_float2(v00 + b0, v01 + b1);
                if (r0 + 8 < NN)
                    *(float2*)&g_resid[(r0 + 8) * HC + cr] = make_float2(v10 + b0, v11 + b1);
            }
        }
    }

    // attention scalars: one (node, head) per thread
    {
        const int n = tid >> 2, p = tid & 3;   // n: 0..127
        float a = 0.f, b = 0.f;
#pragma unroll 16
        for (int k = 0; k < FIN; k++) {
            float xv = __uint_as_float(xs[n * SX + k]);
            a += xv * was[k * 8 + p];
            b += xv * was[k * 8 + 4 + p];
        }
        int node = row0 + n;
        if (node < NN) {
            g_asrc[node * HHD + p] = a;
            g_adst[node * HHD + p] = b;
        }
    }
}

// ---------------- fused aggregate + epilogue (+ counter reset) ---------------
__global__ void __launch_bounds__(512) k_aggregate(
        const float* __restrict__ bias,
        const float* __restrict__ ln_g, const float* __restrict__ ln_b,
        float* __restrict__ out) {
    int node = (blockIdx.x * blockDim.x + threadIdx.x) >> 5;
    if (node >= NN) return;
    const int l  = threadIdx.x & 31;
    const int hh = l >> 3;

    const float ad = g_adst[node * HHD + hh];
    const int beg = g_off[node];
    const int n   = g_deg[node];

    // self-restore counters for the next launch (deterministic every call)
    if (l == 0) {
        g_deg[node] = 0;
        if (node == 0) g_gbase = 0;
    }

    float4 acc = make_float4(0.f, 0.f, 0.f, 0.f);
    float dsum = 0.f;

    for (int base = 0; base < n; base += 32) {
        int id = (base + l < n) ? g_csr_src[beg + base + l] : 0;
        int cnt = min(32, n - base);
#pragma unroll 4
        for (int j = 0; j < cnt; j++) {
            int s = __shfl_sync(0xffffffffu, id, j);
            float as = g_asrc[s * HHD + hh];
            float ex = __expf(lrelu(as + ad));
            uint2 hb = *(const uint2*)&g_h2[s * 64 + l * 2];
            float2 h01 = __half22float2(*(const __half2*)&hb.x);
            float2 h23 = __half22float2(*(const __half2*)&hb.y);
            acc.x += h01.x * ex; acc.y += h01.y * ex;
            acc.z += h23.x * ex; acc.w += h23.y * ex;
            dsum += ex;
        }
    }

    { // self-loop
        float as = g_asrc[node * HHD + hh];
        float ex = __expf(lrelu(as + ad));
        uint2 hb = *(const uint2*)&g_h2[node * 64 + l * 2];
        float2 h01 = __half22float2(*(const __half2*)&hb.x);
        float2 h23 = __half22float2(*(const __half2*)&hb.y);
        acc.x += h01.x * ex; acc.y += h01.y * ex;
        acc.z += h23.x * ex; acc.w += h23.y * ex;
        dsum += ex;
    }

    float inv = 1.f / dsum;
    float4 bv = *(const float4*)&bias[l * 4];
    float4 rv = *(const float4*)&g_resid[node * HC + l * 4];
    float4 v;
    v.x = acc.x * inv + bv.x;  v.y = acc.y * inv + bv.y;
    v.z = acc.z * inv + bv.z;  v.w = acc.w * inv + bv.w;
    v.x = (v.x > 0.f) ? v.x : expm1f(v.x);
    v.y = (v.y > 0.f) ? v.y : expm1f(v.y);
    v.z = (v.z > 0.f) ? v.z : expm1f(v.z);
    v.w = (v.w > 0.f) ? v.w : expm1f(v.w);
    v.x += rv.x; v.y += rv.y; v.z += rv.z; v.w += rv.w;

    float s1 = v.x + v.y + v.z + v.w;
    float s2 = v.x * v.x + v.y * v.y + v.z * v.z + v.w * v.w;
#pragma unroll
    for (int o = 16; o > 0; o >>= 1) {
        s1 += __shfl_xor_sync(0xffffffffu, s1, o);
        s2 += __shfl_xor_sync(0xffffffffu, s2, o);
    }
    float mu  = s1 * (1.f / 128.f);
    float var = s2 * (1.f / 128.f) - mu * mu;
    float r = rsqrtf(var + 1e-5f);

    float4 gv  = *(const float4*)&ln_g[l * 4];
    float4 bbv = *(const float4*)&ln_b[l * 4];
    float4 o4;
    o4.x = gv.x * (v.x - mu) * r + bbv.x;
    o4.y = gv.y * (v.y - mu) * r + bbv.y;
    o4.z = gv.z * (v.z - mu) * r + bbv.z;
    o4.w = gv.w * (v.w - mu) * r + bbv.w;
    *(float4*)&out[node * HC + l * 4] = o4;
}

// ---------------- launch -----------------------------------------------------
extern "C" void kernel_launch(void* const* d_in, const int* in_sizes, int n_in,
                              void* d_out, int out_size) {
    const float* x       = (const float*)d_in[0];
    const int*   ei      = (const int*)d_in[1];
    const float* W       = (const float*)d_in[2];
    const float* att_src = (const float*)d_in[3];
    const float* att_dst = (const float*)d_in[4];
    const float* bias    = (const float*)d_in[5];
    const float* res_w   = (const float*)d_in[6];
    const float* res_b   = (const float*)d_in[7];
    const float* ln_g    = (const float*)d_in[8];
    const float* ln_b    = (const float*)d_in[9];
    float*       out     = (float*)d_out;

    static bool init = false;
    if (!init) {
        cudaFuncSetAttribute(k_gemm_mma,
                             cudaFuncAttributeMaxDynamicSharedMemorySize, GEMM_SMEM);
        init = true;
    }

    k_convert<<<(EE / 4 + 255) / 256, 256>>>(ei);
    k_fold<<<FOLD_BLOCKS, 256>>>(W, att_src, att_dst);

    k_gemm_mma<<<(NN + 127) / 128, 512, GEMM_SMEM>>>(x, W, res_w, res_b);

    k_scan<<<SCAN_GRID, SCAN_B>>>();
    k_scatter<<<(EE / 4 + 255) / 256, 256>>>();

    k_aggregate<<<(NN * 32 + 511) / 512, 512>>>(bias, ln_g, ln_b, out);
}

// round 14
// speedup vs baseline: 1.0643x; 1.0643x over previous
#include <cuda_runtime.h>
#include <cuda_fp16.h>

#define NN 50000
#define EE 800000
#define HHD 4
#define HC 128
#define FIN 64
#define SCAN_B 512
#define SCAN_GRID ((NN + SCAN_B - 1) / SCAN_B)   // 98
#define CONV_B ((EE / 4 + 255) / 256)            // 782 convert blocks
#define FOLD_BLOCKS 64
#define GEMM_GRID ((NN + 127) / 128)             // 391

// ---------------- scratch (device globals; zero-initialized at load) --------
__device__ __align__(16) int      g_src[EE];
__device__ __align__(16) int      g_dst[EE];
__device__ __align__(16) int      g_rank[EE];      // rank of edge within dst
__device__ __align__(16) int      g_csr_src[EE];
__device__ __align__(16) int      g_deg[NN];       // zero at load; reset by aggregate
__device__ __align__(16) int      g_off[NN];
__device__ __align__(16) unsigned g_h2[NN * 64];   // h as half2 pairs
__device__ __align__(16) unsigned g_resid2[NN * 64]; // resid as half2 pairs
__device__ __align__(16) float    g_asrc[NN * HHD];
__device__ __align__(16) float    g_adst[NN * HHD];
__device__ __align__(16) float    g_wa[FIN * 8];   // folded att weights
__device__ int g_gbase;                            // reset by aggregate

// ---------------- helpers ---------------------------------------------------
__device__ __forceinline__ float lrelu(float x) { return x >= 0.f ? x : 0.2f * x; }
__device__ __forceinline__ int clampi(int v) {
    return v < 0 ? 0 : (v >= NN ? NN - 1 : v);
}
__device__ __forceinline__ unsigned f2tf(float f) {
    unsigned u;
    asm("cvt.rna.tf32.f32 %0, %1;" : "=r"(u) : "f"(f));
    return u;
}
__device__ __forceinline__ void mma_tf32(float* d, const unsigned* a,
                                         const unsigned* b) {
    asm volatile(
        "mma.sync.aligned.m16n8k8.row.col.f32.tf32.tf32.f32 "
        "{%0,%1,%2,%3}, {%4,%5,%6,%7}, {%8,%9}, {%0,%1,%2,%3};"
        : "+f"(d[0]), "+f"(d[1]), "+f"(d[2]), "+f"(d[3])
        : "r"(a[0]), "r"(a[1]), "r"(a[2]), "r"(a[3]), "r"(b[0]), "r"(b[1]));
}

// ---------------- launch 1: convert (+rank) + fold ---------------------------
__global__ void k_convert_fold(const int* __restrict__ p,
                               const float* __restrict__ W,
                               const float* __restrict__ att_src,
                               const float* __restrict__ att_dst) {
    int b = blockIdx.x;
    if (b >= CONV_B) {
        // fold: warp per output
        int o = (b - CONV_B) * 8 + (threadIdx.x >> 5);   // 0..511
        int c = threadIdx.x & 31;
        int k = o >> 3, j = o & 7, ph = j & 3;
        const float* att = (j < 4) ? att_src : att_dst;
        float v = W[k * HC + ph * 32 + c] * att[ph * 32 + c];
#pragma unroll
        for (int of = 16; of > 0; of >>= 1)
            v += __shfl_xor_sync(0xffffffffu, v, of);
        if (c == 0) g_wa[o] = v;
        return;
    }
    int t = b * blockDim.x + threadIdx.x;
    int i = t * 4;
    if (i >= EE) return;
    // per-thread dtype probe (int64 view of src region is in-bounds either way)
    int4 a0 = ((const int4*)p)[i / 2];
    int4 a1 = ((const int4*)p)[i / 2 + 1];
    bool is64 = ((a0.y | a0.w | a1.y | a1.w) == 0) &&
                ((unsigned)a0.x < NN) && ((unsigned)a0.z < NN) &&
                ((unsigned)a1.x < NN) && ((unsigned)a1.z < NN);
    int4 sv, dv;
    if (is64) {
        int4 b0 = ((const int4*)p)[(EE + i) / 2];
        int4 b1 = ((const int4*)p)[(EE + i) / 2 + 1];
        sv = make_int4(a0.x, a0.z, a1.x, a1.z);
        dv = make_int4(b0.x, b0.z, b1.x, b1.z);
    } else {
        sv = ((const int4*)p)[i / 4];
        dv = ((const int4*)p)[(EE + i) / 4];
    }
    sv.x = clampi(sv.x); sv.y = clampi(sv.y); sv.z = clampi(sv.z); sv.w = clampi(sv.w);
    dv.x = clampi(dv.x); dv.y = clampi(dv.y); dv.z = clampi(dv.z); dv.w = clampi(dv.w);
    ((int4*)g_src)[i / 4] = sv;
    ((int4*)g_dst)[i / 4] = dv;
    int4 rv;
    rv.x = atomicAdd(&g_deg[dv.x], 1);
    rv.y = atomicAdd(&g_deg[dv.y], 1);
    rv.z = atomicAdd(&g_deg[dv.z], 1);
    rv.w = atomicAdd(&g_deg[dv.w], 1);
    ((int4*)g_rank)[i / 4] = rv;
}

// ---------------- launch 2: scan (blocks 0..97) + GEMM (blocks 98..) ---------
#define SX 68
#define SW 264
#define GEMM_SMEM ((128 * SX + 64 * SW + 512) * 4)   // 104448 B

__global__ void __launch_bounds__(512) k_gemm_scan(
        const float* __restrict__ x, const float* __restrict__ W,
        const float* __restrict__ res_w, const float* __restrict__ res_b) {
    if (blockIdx.x < SCAN_GRID) {
        // ---- scan path: one-pass with atomic base claim ----
        __shared__ int wsm[16];
        __shared__ int base;
        const int tid = threadIdx.x, lane = tid & 31, wid = tid >> 5;
        int idx = blockIdx.x * SCAN_B + tid;
        int v = (idx < NN) ? g_deg[idx] : 0;
        int xi = v;
#pragma unroll
        for (int o = 1; o < 32; o <<= 1) {
            int y = __shfl_up_sync(0xffffffffu, xi, o);
            if (lane >= o) xi += y;
        }
        if (lane == 31) wsm[wid] = xi;
        __syncthreads();
        if (wid == 0 && lane < 16) {
            int t = wsm[lane];
#pragma unroll
            for (int o = 1; o < 16; o <<= 1) {
                int y = __shfl_up_sync(0x0000ffffu, t, o);
                if (lane >= o) t += y;
            }
            wsm[lane] = t;
        }
        __syncthreads();
        if (tid == 0) base = atomicAdd(&g_gbase, wsm[15]);
        __syncthreads();
        int woff = (wid == 0) ? 0 : wsm[wid - 1];
        if (idx < NN) g_off[idx] = base + woff + xi - v;
        return;
    }

    // ---- GEMM path ----
    extern __shared__ unsigned sh[];
    unsigned* xs  = sh;                                 // 128 x SX (tf32 bits)
    unsigned* ws  = sh + 128 * SX;                      // 64 x SW (tf32 bits)
    float*    was = (float*)(sh + 128 * SX + 64 * SW);  // 512

    const int tid  = threadIdx.x;
    const int row0 = (blockIdx.x - SCAN_GRID) * 128;

    if (tid < FIN * 8) was[tid] = g_wa[tid];
    for (int i = tid; i < FIN * 32; i += 512) {
        int k = i >> 5, q = i & 31;
        float4 w1 = ((const float4*)W)[k * 32 + q];
        float4 w2 = ((const float4*)res_w)[k * 32 + q];
        unsigned* p1 = &ws[k * SW + 4 * q];
        unsigned* p2 = &ws[k * SW + 128 + 4 * q];
        p1[0] = f2tf(w1.x); p1[1] = f2tf(w1.y); p1[2] = f2tf(w1.z); p1[3] = f2tf(w1.w);
        p2[0] = f2tf(w2.x); p2[1] = f2tf(w2.y); p2[2] = f2tf(w2.z); p2[3] = f2tf(w2.w);
    }
    for (int i = tid; i < 128 * 16; i += 512) {
        int r = i >> 4, q = i & 15;
        int row = row0 + r;
        float4 xv = (row < NN) ? ((const float4*)x)[row * 16 + q]
                               : make_float4(0.f, 0.f, 0.f, 0.f);
        unsigned* p = &xs[r * SX + 4 * q];
        p[0] = f2tf(xv.x); p[1] = f2tf(xv.y); p[2] = f2tf(xv.z); p[3] = f2tf(xv.w);
    }
    __syncthreads();

    const int warp = tid >> 5, lane = tid & 31;
    const int mw = warp >> 2, nw = warp & 3;             // 4 x 4 warp grid
    const int grp = lane >> 2, tig = lane & 3;
    const int mbase = mw * 32, nbase = nw * 64;

    float acc[2][8][4];
#pragma unroll
    for (int mt = 0; mt < 2; mt++)
#pragma unroll
        for (int nt = 0; nt < 8; nt++)
#pragma unroll
            for (int e = 0; e < 4; e++) acc[mt][nt][e] = 0.f;

#pragma unroll
    for (int kt = 0; kt < 8; kt++) {
        const int k0 = kt * 8;
        unsigned afr[2][4], bfr[8][2];
#pragma unroll
        for (int mt = 0; mt < 2; mt++) {
            int base = (mbase + mt * 16 + grp) * SX + k0 + tig;
            afr[mt][0] = xs[base];
            afr[mt][1] = xs[base + 8 * SX];
            afr[mt][2] = xs[base + 4];
            afr[mt][3] = xs[base + 8 * SX + 4];
        }
#pragma unroll
        for (int nt = 0; nt < 8; nt++) {
            int bb = (k0 + tig) * SW + nbase + nt * 8 + grp;
            bfr[nt][0] = ws[bb];
            bfr[nt][1] = ws[bb + 4 * SW];
        }
#pragma unroll
        for (int mt = 0; mt < 2; mt++)
#pragma unroll
            for (int nt = 0; nt < 8; nt++)
                mma_tf32(acc[mt][nt], afr[mt], bfr[nt]);
    }

    // epilogue: nw 0,1 -> g_h2 ; nw 2,3 -> g_resid2 (+res_b), both fp16
#pragma unroll
    for (int mt = 0; mt < 2; mt++) {
        int r0 = row0 + mbase + mt * 16 + grp;
#pragma unroll
        for (int nt = 0; nt < 8; nt++) {
            int col = nbase + nt * 8 + 2 * tig;
            float v00 = acc[mt][nt][0], v01 = acc[mt][nt][1];
            float v10 = acc[mt][nt][2], v11 = acc[mt][nt][3];
            if (nw < 2) {
                int cp = col >> 1;
                if (r0 < NN)
                    *(__half2*)&g_h2[r0 * 64 + cp] = __floats2half2_rn(v00, v01);
                if (r0 + 8 < NN)
                    *(__half2*)&g_h2[(r0 + 8) * 64 + cp] = __floats2half2_rn(v10, v11);
            } else {
                int cr = col - HC;
                int cp = cr >> 1;
                float b0 = res_b[cr], b1 = res_b[cr + 1];
                if (r0 < NN)
                    *(__half2*)&g_resid2[r0 * 64 + cp] = __floats2half2_rn(v00 + b0, v01 + b1);
                if (r0 + 8 < NN)
                    *(__half2*)&g_resid2[(r0 + 8) * 64 + cp] = __floats2half2_rn(v10 + b0, v11 + b1);
            }
        }
    }

    // attention scalars: one (node, head) per thread
    {
        const int n = tid >> 2, p = tid & 3;   // n: 0..127
        float a = 0.f, b = 0.f;
#pragma unroll 16
        for (int k = 0; k < FIN; k++) {
            float xv = __uint_as_float(xs[n * SX + k]);
            a += xv * was[k * 8 + p];
            b += xv * was[k * 8 + 4 + p];
        }
        int node = row0 + n;
        if (node < NN) {
            g_asrc[node * HHD + p] = a;
            g_adst[node * HHD + p] = b;
        }
    }
}

// ---------------- launch 3: atomic-free scatter ------------------------------
__global__ void k_scatter() {
    int t = blockIdx.x * blockDim.x + threadIdx.x;
    int i = t * 4;
    if (i >= EE) return;
    int4 sv = ((const int4*)g_src)[i / 4];
    int4 dv = ((const int4*)g_dst)[i / 4];
    int4 rv = ((const int4*)g_rank)[i / 4];
    g_csr_src[g_off[dv.x] + rv.x] = sv.x;
    g_csr_src[g_off[dv.y] + rv.y] = sv.y;
    g_csr_src[g_off[dv.z] + rv.z] = sv.z;
    g_csr_src[g_off[dv.w] + rv.w] = sv.w;
}

// ---------------- launch 4: aggregate + epilogue (+ counter reset) -----------
__global__ void __launch_bounds__(512) k_aggregate(
        const float* __restrict__ bias,
        const float* __restrict__ ln_g, const float* __restrict__ ln_b,
        float* __restrict__ out) {
    int node = (blockIdx.x * blockDim.x + threadIdx.x) >> 5;
    if (node >= NN) return;
    const int l  = threadIdx.x & 31;
    const int hh = l >> 3;

    const float ad = g_adst[node * HHD + hh];
    const int beg = g_off[node];
    const int n   = g_deg[node];

    // self-restore counters for the next launch (deterministic every call)
    if (l == 0) {
        g_deg[node] = 0;
        if (node == 0) g_gbase = 0;
    }

    float4 acc = make_float4(0.f, 0.f, 0.f, 0.f);
    float dsum = 0.f;

    for (int base = 0; base < n; base += 32) {
        int id = (base + l < n) ? g_csr_src[beg + base + l] : 0;
        int cnt = min(32, n - base);
#pragma unroll 4
        for (int j = 0; j < cnt; j++) {
            int s = __shfl_sync(0xffffffffu, id, j);
            float as = g_asrc[s * HHD + hh];
            float ex = __expf(lrelu(as + ad));
            uint2 hb = *(const uint2*)&g_h2[s * 64 + l * 2];
            float2 h01 = __half22float2(*(const __half2*)&hb.x);
            float2 h23 = __half22float2(*(const __half2*)&hb.y);
            acc.x += h01.x * ex; acc.y += h01.y * ex;
            acc.z += h23.x * ex; acc.w += h23.y * ex;
            dsum += ex;
        }
    }

    { // self-loop
        float as = g_asrc[node * HHD + hh];
        float ex = __expf(lrelu(as + ad));
        uint2 hb = *(const uint2*)&g_h2[node * 64 + l * 2];
        float2 h01 = __half22float2(*(const __half2*)&hb.x);
        float2 h23 = __half22float2(*(const __half2*)&hb.y);
        acc.x += h01.x * ex; acc.y += h01.y * ex;
        acc.z += h23.x * ex; acc.w += h23.y * ex;
        dsum += ex;
    }

    float inv = 1.f / dsum;
    float4 bv = *(const float4*)&bias[l * 4];
    uint2 rb = *(const uint2*)&g_resid2[node * 64 + l * 2];
    float2 r01 = __half22float2(*(const __half2*)&rb.x);
    float2 r23 = __half22float2(*(const __half2*)&rb.y);
    float4 v;
    v.x = acc.x * inv + bv.x;  v.y = acc.y * inv + bv.y;
    v.z = acc.z * inv + bv.z;  v.w = acc.w * inv + bv.w;
    v.x = (v.x > 0.f) ? v.x : expm1f(v.x);
    v.y = (v.y > 0.f) ? v.y : expm1f(v.y);
    v.z = (v.z > 0.f) ? v.z : expm1f(v.z);
    v.w = (v.w > 0.f) ? v.w : expm1f(v.w);
    v.x += r01.x; v.y += r01.y; v.z += r23.x; v.w += r23.y;

    float s1 = v.x + v.y + v.z + v.w;
    float s2 = v.x * v.x + v.y * v.y + v.z * v.z + v.w * v.w;
#pragma unroll
    for (int o = 16; o > 0; o >>= 1) {
        s1 += __shfl_xor_sync(0xffffffffu, s1, o);
        s2 += __shfl_xor_sync(0xffffffffu, s2, o);
    }
    float mu  = s1 * (1.f / 128.f);
    float var = s2 * (1.f / 128.f) - mu * mu;
    float r = rsqrtf(var + 1e-5f);

    float4 gv  = *(const float4*)&ln_g[l * 4];
    float4 bbv = *(const float4*)&ln_b[l * 4];
    float4 o4;
    o4.x = gv.x * (v.x - mu) * r + bbv.x;
    o4.y = gv.y * (v.y - mu) * r + bbv.y;
    o4.z = gv.z * (v.z - mu) * r + bbv.z;
    o4.w = gv.w * (v.w - mu) * r + bbv.w;
    *(float4*)&out[node * HC + l * 4] = o4;
}

// ---------------- launch -----------------------------------------------------
extern "C" void kernel_launch(void* const* d_in, const int* in_sizes, int n_in,
                              void* d_out, int out_size) {
    const float* x       = (const float*)d_in[0];
    const int*   ei      = (const int*)d_in[1];
    const float* W       = (const float*)d_in[2];
    const float* att_src = (const float*)d_in[3];
    const float* att_dst = (const float*)d_in[4];
    const float* bias    = (const float*)d_in[5];
    const float* res_w   = (const float*)d_in[6];
    const float* res_b   = (const float*)d_in[7];
    const float* ln_g    = (const float*)d_in[8];
    const float* ln_b    = (const float*)d_in[9];
    float*       out     = (float*)d_out;

    static bool init = false;
    if (!init) {
        cudaFuncSetAttribute(k_gemm_scan,
                             cudaFuncAttributeMaxDynamicSharedMemorySize, GEMM_SMEM);
        init = true;
    }

    k_convert_fold<<<CONV_B + FOLD_BLOCKS, 256>>>(ei, W, att_src, att_dst);
    k_gemm_scan<<<SCAN_GRID + GEMM_GRID, 512, GEMM_SMEM>>>(x, W, res_w, res_b);
    k_scatter<<<(EE / 4 + 255) / 256, 256>>>();
    k_aggregate<<<(NN * 32 + 511) / 512, 512>>>(bias, ln_g, ln_b, out);
}